// round 13
// baseline (speedup 1.0000x reference)
#include <cuda_runtime.h>
#include <cstdint>
#include <cstddef>

#define BB 8
#define NN 8192
#define DD 3
#define CC 64
#define MM 2048
#define KK 32
#define CIN 67
#define HID 268
#define OUTD 128

__device__ int g_nbr[BB * MM * KK];
__device__ float g_w2dup[HID * 256];  // w2 with each element duplicated: (w,w)

// ---------------- packed f32x2 helpers (per-lane IEEE rn == scalar) ----------
typedef unsigned long long u64;
static __device__ __forceinline__ u64 pk2(float lo, float hi) {
    u64 r;
    asm("mov.b64 %0, {%1, %2};" : "=l"(r) : "f"(lo), "f"(hi));
    return r;
}
static __device__ __forceinline__ void upk2(u64 v, float& lo, float& hi) {
    asm("mov.b64 {%0, %1}, %2;" : "=f"(lo), "=f"(hi) : "l"(v));
}
static __device__ __forceinline__ u64 f2add(u64 a, u64 b) {
    u64 r;
    asm("add.rn.f32x2 %0, %1, %2;" : "=l"(r) : "l"(a), "l"(b));
    return r;
}
static __device__ __forceinline__ u64 f2mul(u64 a, u64 b) {
    u64 r;
    asm("mul.rn.f32x2 %0, %1, %2;" : "=l"(r) : "l"(a), "l"(b));
    return r;
}
static __device__ __forceinline__ u64 f2fma(u64 a, u64 b, u64 c) {
    u64 r;
    asm("fma.rn.f32x2 %0, %1, %2, %3;" : "=l"(r) : "l"(a), "l"(b), "l"(c));
    return r;
}

// ---------------------------------------------------------------------------
// Prep: duplicate w2 -> g_w2dup[j][2c] = g_w2dup[j][2c+1] = w2[j][c]
// ---------------------------------------------------------------------------
__global__ void dupw2_kernel(const float* __restrict__ w2) {
    int idx = blockIdx.x * blockDim.x + threadIdx.x;
    if (idx < HID * OUTD) {
        int j = idx >> 7, c = idx & 127;
        float v = w2[idx];
        *(float2*)&g_w2dup[j * 256 + 2 * c] = make_float2(v, v);
    }
}

// ---------------------------------------------------------------------------
// FPS v4 (unchanged from R12, 911us): one block/batch, 1024 threads, 8
// pts/thread packed. Distance bits identical: add(neg), mul, fma, fma (rn).
// ---------------------------------------------------------------------------
__global__ void __launch_bounds__(1024) fps_kernel(
    const float* __restrict__ x, const int* __restrict__ first_idx,
    float* __restrict__ centers) {
    constexpr int T = 1024;
    constexpr int PPT = NN / T;  // 8
    extern __shared__ float sh[];
    float* sxc = sh;
    float* syc = sh + NN;
    float* szc = sh + 2 * NN;
    __shared__ unsigned s_red[2][32];
    __shared__ int s_far[2];

    int b = blockIdx.x, t = threadIdx.x;
    int lane = t & 31, warp = t >> 5;
    const float* xb = x + (size_t)b * NN * 3;

    u64 px2[PPT / 2], py2[PPT / 2], pz2[PPT / 2];
    float d[PPT];
#pragma unroll
    for (int j = 0; j < PPT / 2; j++) {
        int n0 = t + T * (2 * j), n1 = t + T * (2 * j + 1);
        float ax = xb[n0 * 3 + 0], ay = xb[n0 * 3 + 1], az = xb[n0 * 3 + 2];
        float bx = xb[n1 * 3 + 0], by = xb[n1 * 3 + 1], bz = xb[n1 * 3 + 2];
        sxc[n0] = ax; syc[n0] = ay; szc[n0] = az;
        sxc[n1] = bx; syc[n1] = by; szc[n1] = bz;
        px2[j] = pk2(ax, bx); py2[j] = pk2(ay, by); pz2[j] = pk2(az, bz);
    }
    if (t == 0) { s_far[0] = 0x7fffffff; s_far[1] = 0x7fffffff; }
    int fi = first_idx[b];
    __syncthreads();

    float fx = sxc[fi], fy = syc[fi], fz = szc[fi];
    if (t == 0) {
        float* c = centers + (size_t)b * MM * 3;
        c[0] = fx; c[1] = fy; c[2] = fz;
    }
    float tmax = -1.0f;
    {
        u64 nfx = pk2(-fx, -fx), nfy = pk2(-fy, -fy), nfz = pk2(-fz, -fz);
#pragma unroll
        for (int j = 0; j < PPT / 2; j++) {
            u64 dxp = f2add(px2[j], nfx);
            u64 dyp = f2add(py2[j], nfy);
            u64 dzp = f2add(pz2[j], nfz);
            u64 dd = f2fma(dzp, dzp, f2fma(dyp, dyp, f2mul(dxp, dxp)));
            upk2(dd, d[2 * j], d[2 * j + 1]);
            tmax = fmaxf(tmax, d[2 * j]);
            tmax = fmaxf(tmax, d[2 * j + 1]);
        }
    }

    for (int it = 1; it < MM; it++) {
        int par = it & 1;
        unsigned tb = __float_as_uint(tmax);  // all d >= 0: uint order == float
        unsigned wm = __reduce_max_sync(0xffffffffu, tb);
        if (lane == 0) s_red[par][warp] = wm;
        __syncthreads();
        unsigned gb = __reduce_max_sync(0xffffffffu, s_red[par][lane]);
        if (tb == gb) {
            int bim = 0x7fffffff;
#pragma unroll
            for (int s = PPT - 1; s >= 0; s--)
                if (__float_as_uint(d[s]) == gb) bim = t + T * s;
            atomicMin(&s_far[par], bim);
        }
        if (t == 0) s_far[par ^ 1] = 0x7fffffff;
        __syncthreads();
        int far = s_far[par];
        fx = sxc[far]; fy = syc[far]; fz = szc[far];
        if (t == 0) {
            float* c = centers + ((size_t)b * MM + it) * 3;
            c[0] = fx; c[1] = fy; c[2] = fz;
        }
        u64 nfx = pk2(-fx, -fx), nfy = pk2(-fy, -fy), nfz = pk2(-fz, -fz);
        tmax = -1.0f;
#pragma unroll
        for (int j = 0; j < PPT / 2; j++) {
            u64 dxp = f2add(px2[j], nfx);
            u64 dyp = f2add(py2[j], nfy);
            u64 dzp = f2add(pz2[j], nfz);
            u64 dd = f2fma(dzp, dzp, f2fma(dyp, dyp, f2mul(dxp, dxp)));
            float n0, n1;
            upk2(dd, n0, n1);
            d[2 * j] = fminf(d[2 * j], n0);
            d[2 * j + 1] = fminf(d[2 * j + 1], n1);
            tmax = fmaxf(tmax, d[2 * j]);
            tmax = fmaxf(tmax, d[2 * j + 1]);
        }
    }
}

// ---------------------------------------------------------------------------
// Ball query: unchanged (distance/selection bits identical).
// ---------------------------------------------------------------------------
__global__ void bq_kernel(const float* __restrict__ x,
                          const float* __restrict__ centers,
                          int* __restrict__ nbr) {
    constexpr int WPB = 4;
    constexpr int TILE = 2048;
    __shared__ float sx[TILE * 3];

    int w = threadIdx.x >> 5;
    int lane = threadIdx.x & 31;
    int cid = blockIdx.x * WPB + w;
    int b = cid >> 11;
    const float* xb = x + (size_t)b * NN * 3;

    float cx, cy, cz;
    {
        const float* c = centers + (size_t)cid * 3;
        cx = c[0]; cy = c[1]; cz = c[2];
    }
    const float r2 = 0.09f;
    float sd2 = __int_as_float(0x7f800000);
    int sidx = NN - 1;

    for (int tile = 0; tile < NN / TILE; tile++) {
        __syncthreads();
        const float4* src = (const float4*)(xb + tile * TILE * 3);
        for (int i = threadIdx.x; i < TILE * 3 / 4; i += WPB * 32)
            ((float4*)sx)[i] = src[i];
        __syncthreads();
        int base = tile * TILE;
        for (int i0 = 0; i0 < TILE; i0 += 32) {
            int i = i0 + lane;
            float dx = __fsub_rn(sx[3 * i + 0], cx);
            float dy = __fsub_rn(sx[3 * i + 1], cy);
            float dz = __fsub_rn(sx[3 * i + 2], cz);
            float d2 = __fmaf_rn(dz, dz, __fmaf_rn(dy, dy, __fmul_rn(dx, dx)));
            unsigned m = __ballot_sync(0xffffffffu, d2 < r2);
            while (m) {
                int src_l = __ffs(m) - 1;
                m &= m - 1;
                float cd2 = __shfl_sync(0xffffffffu, d2, src_l);
                unsigned mx = __reduce_max_sync(0xffffffffu, __float_as_uint(sd2));
                if (__float_as_uint(cd2) < mx) {
                    unsigned who =
                        __ballot_sync(0xffffffffu, __float_as_uint(sd2) == mx);
                    if (lane == __ffs(who) - 1) {
                        sd2 = cd2;
                        sidx = base + i0 + src_l;
                    }
                }
            }
        }
    }
    nbr[cid * KK + lane] = (sd2 < r2) ? sidx : (NN - 1);
}

// fast tanh-gelu: exp2-based tanh (MUFU). Continuous op, ~1e-6 effect.
static __device__ __forceinline__ float fast_gelu(float h) {
    float u = 0.7978845608028654f * __fmaf_rn(0.044715f * h, h * h, h);
    u = fminf(fmaxf(u, -9.0f), 9.0f);
    float e = __expf(2.0f * u);
    float t = (e - 1.0f) * __frcp_rn(e + 1.0f);
    return 0.5f * h * (1.0f + t);
}

// ---------------------------------------------------------------------------
// Fused MLP v5: layouts arranged so every FFMA2 operand is a free pack:
//  - comb stored duplicated (c,c) -> activation pairs from LDS.128 (2 i / ld)
//  - weights (layer 1) via LDG float4 -> pairs are aligned reg quads (free)
//  - h1 stored TRANSPOSED [268][36] -> row-pair activations via LDS.64 (free)
//  - w2 pre-duplicated in global -> dup weight pairs via LDG.128 (free)
// Accumulation order per accumulator unchanged -> bitwise identical results.
// ---------------------------------------------------------------------------
__global__ void __launch_bounds__(128)
mlp_kernel(const float* __restrict__ x, const float* __restrict__ feat,
           const float* __restrict__ centers, const int* __restrict__ nbr,
           const float* __restrict__ w1, const float* __restrict__ b1,
           const float* __restrict__ g1, const float* __restrict__ be1,
           const float* __restrict__ b2,
           const float* __restrict__ g2, const float* __restrict__ be2,
           float* __restrict__ out) {
    __shared__ __align__(16) float s_h1T[HID][36];  // transposed h1 (pad 36)
    __shared__ float s_wmax[4][128];
    __shared__ int s_nbr[32];
    __shared__ float s_ctr[3];

    // comb duplicated overlay: [32][136], dead before h1T is written
    float (*s_combD)[136] = (float(*)[136]) & s_h1T[0][0];

    int cid = blockIdx.x;
    int b = cid >> 11;
    int tid = threadIdx.x, w = tid >> 5, l = tid & 31;
    const int k0 = 8 * w;

    if (tid < 32) s_nbr[tid] = nbr[cid * KK + tid];
    if (tid < 3) s_ctr[tid] = centers[(size_t)cid * 3 + tid];
    __syncthreads();

    // gather comb duplicated: [f(64) dup -> 128 floats][rel(3) dup -> 6]
#pragma unroll
    for (int r = 0; r < 8; r++) {
        int k = k0 + r;
        int idx = s_nbr[k];
        const float2* frow = (const float2*)(feat + ((size_t)b * NN + idx) * CC);
        float2 v = frow[l];
        *(float4*)&s_combD[k][4 * l] = make_float4(v.x, v.x, v.y, v.y);
        if (l == 0) {
            const float* p = x + ((size_t)b * NN + idx) * 3;
            float r0 = p[0] - s_ctr[0];
            float r1 = p[1] - s_ctr[1];
            float r2v = p[2] - s_ctr[2];
            s_combD[k][128] = r0; s_combD[k][129] = r0;
            s_combD[k][130] = r1; s_combD[k][131] = r1;
            s_combD[k][132] = r2v; s_combD[k][133] = r2v;
        }
    }
    __syncthreads();

    // ---- layer 1: lane cols 4l..4l+3, 128+4l..+3, 256+l (l<12); 8 rows/warp
    const int jA = 4 * l, jB = 128 + 4 * l, jC = 256 + l;
    const bool hasC = (l < 12);

    u64 accP[8][4];
    float acc9[8];
#pragma unroll
    for (int r = 0; r < 8; r++) {
        acc9[r] = 0.f;
#pragma unroll
        for (int q = 0; q < 4; q++) accP[r][q] = 0ull;
    }

    for (int i2 = 0; i2 < 33; i2++) {  // i = 2*i2, 2*i2+1 (0..65)
        ulonglong2 apq[8];
#pragma unroll
        for (int r = 0; r < 8; r++)
            apq[r] = *(const ulonglong2*)&s_combD[k0 + r][4 * i2];
#pragma unroll
        for (int half = 0; half < 2; half++) {
            int i = 2 * i2 + half;
            const float* wr = w1 + (size_t)i * HID;
            float4 wa = *(const float4*)(wr + jA);
            float4 wb = *(const float4*)(wr + jB);
            float wc = hasC ? wr[jC] : 0.f;
            u64 pw0 = pk2(wa.x, wa.y), pw1 = pk2(wa.z, wa.w);
            u64 pw2 = pk2(wb.x, wb.y), pw3 = pk2(wb.z, wb.w);
#pragma unroll
            for (int r = 0; r < 8; r++) {
                u64 cp = half ? apq[r].y : apq[r].x;  // (c,c) pre-duplicated
                accP[r][0] = f2fma(cp, pw0, accP[r][0]);
                accP[r][1] = f2fma(cp, pw1, accP[r][1]);
                accP[r][2] = f2fma(cp, pw2, accP[r][2]);
                accP[r][3] = f2fma(cp, pw3, accP[r][3]);
                float clo, chi;
                upk2(cp, clo, chi);  // register alias, no MOV
                acc9[r] = __fmaf_rn(clo, wc, acc9[r]);
            }
        }
    }
    {  // tail i = 66
        const float* wr = w1 + (size_t)66 * HID;
        float4 wa = *(const float4*)(wr + jA);
        float4 wb = *(const float4*)(wr + jB);
        float wc = hasC ? wr[jC] : 0.f;
        u64 pw0 = pk2(wa.x, wa.y), pw1 = pk2(wa.z, wa.w);
        u64 pw2 = pk2(wb.x, wb.y), pw3 = pk2(wb.z, wb.w);
#pragma unroll
        for (int r = 0; r < 8; r++) {
            u64 cp = *(const u64*)&s_combD[k0 + r][132];
            accP[r][0] = f2fma(cp, pw0, accP[r][0]);
            accP[r][1] = f2fma(cp, pw1, accP[r][1]);
            accP[r][2] = f2fma(cp, pw2, accP[r][2]);
            accP[r][3] = f2fma(cp, pw3, accP[r][3]);
            float clo, chi;
            upk2(cp, clo, chi);
            acc9[r] = __fmaf_rn(clo, wc, acc9[r]);
        }
    }

    // all combD reads done block-wide before h1T (overlay) is written
    __syncthreads();

    float acc[8][9];
#pragma unroll
    for (int r = 0; r < 8; r++) {
        upk2(accP[r][0], acc[r][0], acc[r][1]);
        upk2(accP[r][1], acc[r][2], acc[r][3]);
        upk2(accP[r][2], acc[r][4], acc[r][5]);
        upk2(accP[r][3], acc[r][6], acc[r][7]);
        acc[r][8] = acc9[r];
    }

    // bias + gelu
    {
        float4 bA = *(const float4*)(b1 + jA);
        float4 bB = *(const float4*)(b1 + jB);
        float bC = hasC ? b1[jC] : 0.f;
        float bias[9] = {bA.x, bA.y, bA.z, bA.w, bB.x, bB.y, bB.z, bB.w, bC};
#pragma unroll
        for (int r = 0; r < 8; r++)
#pragma unroll
            for (int c = 0; c < 9; c++)
                acc[r][c] = fast_gelu(acc[r][c] + bias[c]);
    }

    // LN over 268 (warp-wide)
    float sum[8], sq[8];
#pragma unroll
    for (int r = 0; r < 8; r++) {
        float s = 0.f, q = 0.f;
#pragma unroll
        for (int c = 0; c < 8; c++) {
            s += acc[r][c];
            q += acc[r][c] * acc[r][c];
        }
        if (hasC) {
            s += acc[r][8];
            q += acc[r][8] * acc[r][8];
        }
        sum[r] = s;
        sq[r] = q;
    }
#pragma unroll
    for (int o = 16; o; o >>= 1) {
#pragma unroll
        for (int r = 0; r < 8; r++) {
            sum[r] += __shfl_xor_sync(0xffffffffu, sum[r], o);
            sq[r] += __shfl_xor_sync(0xffffffffu, sq[r], o);
        }
    }
    {
        float4 gA = *(const float4*)(g1 + jA);
        float4 gB = *(const float4*)(g1 + jB);
        float gC = hasC ? g1[jC] : 0.f;
        float4 eA = *(const float4*)(be1 + jA);
        float4 eB = *(const float4*)(be1 + jB);
        float eC = hasC ? be1[jC] : 0.f;
        float gam[9] = {gA.x, gA.y, gA.z, gA.w, gB.x, gB.y, gB.z, gB.w, gC};
        float bet[9] = {eA.x, eA.y, eA.z, eA.w, eB.x, eB.y, eB.z, eB.w, eC};
#pragma unroll
        for (int r = 0; r < 8; r++) {
            float mu = sum[r] * (1.0f / 268.0f);
            float var = sq[r] * (1.0f / 268.0f) - mu * mu;
            float inv = rsqrtf(var + 1e-6f);
            int k = k0 + r;
            // transposed store: h1T[j][k]
#pragma unroll
            for (int c = 0; c < 4; c++)
                s_h1T[jA + c][k] = (acc[r][c] - mu) * inv * gam[c] + bet[c];
#pragma unroll
            for (int c = 0; c < 4; c++)
                s_h1T[jB + c][k] = (acc[r][4 + c] - mu) * inv * gam[4 + c] + bet[4 + c];
            if (hasC)
                s_h1T[jC][k] = (acc[r][8] - mu) * inv * gam[8] + bet[8];
        }
    }
    __syncthreads();

    // ---- layer 2: row-pair packed (rows k0+2p,k0+2p+1), lane cols 4l..4l+3
    const int o0 = 4 * l;
    u64 a2p[4][4];  // [row-pair][col]
#pragma unroll
    for (int p = 0; p < 4; p++)
#pragma unroll
        for (int c = 0; c < 4; c++) a2p[p][c] = 0ull;

    const float* wdup = g_w2dup + 8 * l;
    for (int j = 0; j < HID; j++) {
        u64 hp[4];
#pragma unroll
        for (int p = 0; p < 4; p++)
            hp[p] = *(const u64*)&s_h1T[j][k0 + 2 * p];  // (h_r0, h_r1) free
        const float4* wd = (const float4*)(wdup + (size_t)j * 256);
        float4 w01 = wd[0], w23 = wd[1];  // (w,w,w',w') duplicated
        u64 pw0 = pk2(w01.x, w01.y), pw1 = pk2(w01.z, w01.w);
        u64 pw2 = pk2(w23.x, w23.y), pw3 = pk2(w23.z, w23.w);
#pragma unroll
        for (int p = 0; p < 4; p++) {
            a2p[p][0] = f2fma(hp[p], pw0, a2p[p][0]);
            a2p[p][1] = f2fma(hp[p], pw1, a2p[p][1]);
            a2p[p][2] = f2fma(hp[p], pw2, a2p[p][2]);
            a2p[p][3] = f2fma(hp[p], pw3, a2p[p][3]);
        }
    }

    float a2[8][4];
#pragma unroll
    for (int p = 0; p < 4; p++)
#pragma unroll
        for (int c = 0; c < 4; c++)
            upk2(a2p[p][c], a2[2 * p][c], a2[2 * p + 1][c]);
    {
        float4 bv = *(const float4*)(b2 + o0);
        float bias[4] = {bv.x, bv.y, bv.z, bv.w};
#pragma unroll
        for (int r = 0; r < 8; r++)
#pragma unroll
            for (int c = 0; c < 4; c++) a2[r][c] += bias[c];
    }
    // LN over 128 (warp-wide)
    float s2[8], q2[8];
#pragma unroll
    for (int r = 0; r < 8; r++) {
        float s = 0.f, q = 0.f;
#pragma unroll
        for (int c = 0; c < 4; c++) {
            s += a2[r][c];
            q += a2[r][c] * a2[r][c];
        }
        s2[r] = s;
        q2[r] = q;
    }
#pragma unroll
    for (int o = 16; o; o >>= 1) {
#pragma unroll
        for (int r = 0; r < 8; r++) {
            s2[r] += __shfl_xor_sync(0xffffffffu, s2[r], o);
            q2[r] += __shfl_xor_sync(0xffffffffu, q2[r], o);
        }
    }
    {
        float4 gv = *(const float4*)(g2 + o0);
        float4 ev = *(const float4*)(be2 + o0);
        float gam[4] = {gv.x, gv.y, gv.z, gv.w};
        float bet[4] = {ev.x, ev.y, ev.z, ev.w};
        float cmax[4];
#pragma unroll
        for (int c = 0; c < 4; c++) cmax[c] = -3.4e38f;
#pragma unroll
        for (int r = 0; r < 8; r++) {
            float mu = s2[r] * (1.0f / 128.0f);
            float var = q2[r] * (1.0f / 128.0f) - mu * mu;
            float inv = rsqrtf(var + 1e-6f);
#pragma unroll
            for (int c = 0; c < 4; c++) {
                float v = (a2[r][c] - mu) * inv * gam[c] + bet[c];
                cmax[c] = fmaxf(cmax[c], v);
            }
        }
#pragma unroll
        for (int c = 0; c < 4; c++) s_wmax[w][o0 + c] = cmax[c];
    }
    __syncthreads();
    if (tid < 128) {
        float m = s_wmax[0][tid];
#pragma unroll
        for (int ww = 1; ww < 4; ww++) m = fmaxf(m, s_wmax[ww][tid]);
        out[(size_t)cid * OUTD + tid] = m;
    }
}

// ---------------------------------------------------------------------------
extern "C" void kernel_launch(void* const* d_in, const int* in_sizes, int n_in,
                              void* d_out, int out_size) {
    const float* x = (const float*)d_in[0];
    const float* feat = (const float*)d_in[1];
    const int* first_idx = (const int*)d_in[2];
    const float* w1 = (const float*)d_in[3];
    const float* b1 = (const float*)d_in[4];
    const float* g1 = (const float*)d_in[5];
    const float* be1 = (const float*)d_in[6];
    const float* w2 = (const float*)d_in[7];
    const float* b2 = (const float*)d_in[8];
    const float* g2 = (const float*)d_in[9];
    const float* be2 = (const float*)d_in[10];

    float* centers = (float*)d_out;                    // [B, M, 3]
    float* out = (float*)d_out + (size_t)BB * MM * 3;  // [B, M, 128]

    int* nbr;
    cudaGetSymbolAddress((void**)&nbr, g_nbr);

    const int fps_smem = 3 * NN * (int)sizeof(float);  // 96KB coords mirror
    cudaFuncSetAttribute(fps_kernel, cudaFuncAttributeMaxDynamicSharedMemorySize,
                         fps_smem);

    dupw2_kernel<<<(HID * OUTD + 255) / 256, 256>>>(w2);
    fps_kernel<<<BB, 1024, fps_smem>>>(x, first_idx, centers);
    bq_kernel<<<BB * MM / 4, 128>>>(x, centers, nbr);
    mlp_kernel<<<BB * MM, 128>>>(x, feat, centers, nbr, w1, b1, g1, be1, b2,
                                 g2, be2, out);
}

// round 15
// speedup vs baseline: 1.2199x; 1.2199x over previous
#include <cuda_runtime.h>
#include <cstdint>
#include <cstddef>

#define BB 8
#define NN 8192
#define DD 3
#define CC 64
#define MM 2048
#define KK 32
#define CIN 67
#define HID 268
#define OUTD 128

__device__ int g_nbr[BB * MM * KK];

// ---------------- packed f32x2 helpers (per-lane IEEE rn == scalar) ----------
typedef unsigned long long u64;
static __device__ __forceinline__ u64 pk2(float lo, float hi) {
    u64 r;
    asm("mov.b64 %0, {%1, %2};" : "=l"(r) : "f"(lo), "f"(hi));
    return r;
}
static __device__ __forceinline__ void upk2(u64 v, float& lo, float& hi) {
    asm("mov.b64 {%0, %1}, %2;" : "=f"(lo), "=f"(hi) : "l"(v));
}
static __device__ __forceinline__ u64 f2add(u64 a, u64 b) {
    u64 r;
    asm("add.rn.f32x2 %0, %1, %2;" : "=l"(r) : "l"(a), "l"(b));
    return r;
}
static __device__ __forceinline__ u64 f2mul(u64 a, u64 b) {
    u64 r;
    asm("mul.rn.f32x2 %0, %1, %2;" : "=l"(r) : "l"(a), "l"(b));
    return r;
}
static __device__ __forceinline__ u64 f2fma(u64 a, u64 b, u64 c) {
    u64 r;
    asm("fma.rn.f32x2 %0, %1, %2, %3;" : "=l"(r) : "l"(a), "l"(b), "l"(c));
    return r;
}

// ---------------------------------------------------------------------------
// FPS v4 (measured 911us in R12): one block/batch, 1024 threads, 8 pts/thread
// packed. Distance bits identical: add(neg), mul, fma, fma (rn each).
// Selection: global max, then min index among maxima (atomicMin).
// ---------------------------------------------------------------------------
__global__ void __launch_bounds__(1024) fps_kernel(
    const float* __restrict__ x, const int* __restrict__ first_idx,
    float* __restrict__ centers) {
    constexpr int T = 1024;
    constexpr int PPT = NN / T;  // 8
    extern __shared__ float sh[];
    float* sxc = sh;
    float* syc = sh + NN;
    float* szc = sh + 2 * NN;
    __shared__ unsigned s_red[2][32];
    __shared__ int s_far[2];

    int b = blockIdx.x, t = threadIdx.x;
    int lane = t & 31, warp = t >> 5;
    const float* xb = x + (size_t)b * NN * 3;

    u64 px2[PPT / 2], py2[PPT / 2], pz2[PPT / 2];
    float d[PPT];
#pragma unroll
    for (int j = 0; j < PPT / 2; j++) {
        int n0 = t + T * (2 * j), n1 = t + T * (2 * j + 1);
        float ax = xb[n0 * 3 + 0], ay = xb[n0 * 3 + 1], az = xb[n0 * 3 + 2];
        float bx = xb[n1 * 3 + 0], by = xb[n1 * 3 + 1], bz = xb[n1 * 3 + 2];
        sxc[n0] = ax; syc[n0] = ay; szc[n0] = az;
        sxc[n1] = bx; syc[n1] = by; szc[n1] = bz;
        px2[j] = pk2(ax, bx); py2[j] = pk2(ay, by); pz2[j] = pk2(az, bz);
    }
    if (t == 0) { s_far[0] = 0x7fffffff; s_far[1] = 0x7fffffff; }
    int fi = first_idx[b];
    __syncthreads();

    float fx = sxc[fi], fy = syc[fi], fz = szc[fi];
    if (t == 0) {
        float* c = centers + (size_t)b * MM * 3;
        c[0] = fx; c[1] = fy; c[2] = fz;
    }
    float tmax = -1.0f;
    {
        u64 nfx = pk2(-fx, -fx), nfy = pk2(-fy, -fy), nfz = pk2(-fz, -fz);
#pragma unroll
        for (int j = 0; j < PPT / 2; j++) {
            u64 dxp = f2add(px2[j], nfx);
            u64 dyp = f2add(py2[j], nfy);
            u64 dzp = f2add(pz2[j], nfz);
            u64 dd = f2fma(dzp, dzp, f2fma(dyp, dyp, f2mul(dxp, dxp)));
            upk2(dd, d[2 * j], d[2 * j + 1]);
            tmax = fmaxf(tmax, d[2 * j]);
            tmax = fmaxf(tmax, d[2 * j + 1]);
        }
    }

    for (int it = 1; it < MM; it++) {
        int par = it & 1;
        unsigned tb = __float_as_uint(tmax);  // all d >= 0: uint order == float
        unsigned wm = __reduce_max_sync(0xffffffffu, tb);
        if (lane == 0) s_red[par][warp] = wm;
        __syncthreads();
        unsigned gb = __reduce_max_sync(0xffffffffu, s_red[par][lane]);
        if (tb == gb) {
            int bim = 0x7fffffff;
#pragma unroll
            for (int s = PPT - 1; s >= 0; s--)
                if (__float_as_uint(d[s]) == gb) bim = t + T * s;
            atomicMin(&s_far[par], bim);
        }
        if (t == 0) s_far[par ^ 1] = 0x7fffffff;
        __syncthreads();
        int far = s_far[par];
        fx = sxc[far]; fy = syc[far]; fz = szc[far];
        if (t == 0) {
            float* c = centers + ((size_t)b * MM + it) * 3;
            c[0] = fx; c[1] = fy; c[2] = fz;
        }
        u64 nfx = pk2(-fx, -fx), nfy = pk2(-fy, -fy), nfz = pk2(-fz, -fz);
        tmax = -1.0f;
#pragma unroll
        for (int j = 0; j < PPT / 2; j++) {
            u64 dxp = f2add(px2[j], nfx);
            u64 dyp = f2add(py2[j], nfy);
            u64 dzp = f2add(pz2[j], nfz);
            u64 dd = f2fma(dzp, dzp, f2fma(dyp, dyp, f2mul(dxp, dxp)));
            float n0, n1;
            upk2(dd, n0, n1);
            d[2 * j] = fminf(d[2 * j], n0);
            d[2 * j + 1] = fminf(d[2 * j + 1], n1);
            tmax = fmaxf(tmax, d[2 * j]);
            tmax = fmaxf(tmax, d[2 * j + 1]);
        }
    }
}

// ---------------------------------------------------------------------------
// Ball query: unchanged (distance/selection bits identical).
// ---------------------------------------------------------------------------
__global__ void bq_kernel(const float* __restrict__ x,
                          const float* __restrict__ centers,
                          int* __restrict__ nbr) {
    constexpr int WPB = 4;
    constexpr int TILE = 2048;
    __shared__ float sx[TILE * 3];

    int w = threadIdx.x >> 5;
    int lane = threadIdx.x & 31;
    int cid = blockIdx.x * WPB + w;
    int b = cid >> 11;
    const float* xb = x + (size_t)b * NN * 3;

    float cx, cy, cz;
    {
        const float* c = centers + (size_t)cid * 3;
        cx = c[0]; cy = c[1]; cz = c[2];
    }
    const float r2 = 0.09f;
    float sd2 = __int_as_float(0x7f800000);
    int sidx = NN - 1;

    for (int tile = 0; tile < NN / TILE; tile++) {
        __syncthreads();
        const float4* src = (const float4*)(xb + tile * TILE * 3);
        for (int i = threadIdx.x; i < TILE * 3 / 4; i += WPB * 32)
            ((float4*)sx)[i] = src[i];
        __syncthreads();
        int base = tile * TILE;
        for (int i0 = 0; i0 < TILE; i0 += 32) {
            int i = i0 + lane;
            float dx = __fsub_rn(sx[3 * i + 0], cx);
            float dy = __fsub_rn(sx[3 * i + 1], cy);
            float dz = __fsub_rn(sx[3 * i + 2], cz);
            float d2 = __fmaf_rn(dz, dz, __fmaf_rn(dy, dy, __fmul_rn(dx, dx)));
            unsigned m = __ballot_sync(0xffffffffu, d2 < r2);
            while (m) {
                int src_l = __ffs(m) - 1;
                m &= m - 1;
                float cd2 = __shfl_sync(0xffffffffu, d2, src_l);
                unsigned mx = __reduce_max_sync(0xffffffffu, __float_as_uint(sd2));
                if (__float_as_uint(cd2) < mx) {
                    unsigned who =
                        __ballot_sync(0xffffffffu, __float_as_uint(sd2) == mx);
                    if (lane == __ffs(who) - 1) {
                        sd2 = cd2;
                        sidx = base + i0 + src_l;
                    }
                }
            }
        }
    }
    nbr[cid * KK + lane] = (sd2 < r2) ? sidx : (NN - 1);
}

// fast tanh-gelu: exp2-based tanh (MUFU). Continuous op, ~1e-6 effect.
static __device__ __forceinline__ float fast_gelu(float h) {
    float u = 0.7978845608028654f * __fmaf_rn(0.044715f * h, h * h, h);
    u = fminf(fmaxf(u, -9.0f), 9.0f);
    float e = __expf(2.0f * u);
    float t = (e - 1.0f) * __frcp_rn(e + 1.0f);
    return 0.5f * h * (1.0f + t);
}

// ---------------------------------------------------------------------------
// Fused MLP v3 (the measured-best variant from R9, ~1.40ms): one block/center,
// 128 threads (4 warps), 8 rows/warp, packed f32x2 FMA, LDG weight path,
// s_comb overlaying s_h1. All arithmetic bit-identical to R8/R9.
// ---------------------------------------------------------------------------
__global__ void __launch_bounds__(128)
mlp_kernel(const float* __restrict__ x, const float* __restrict__ feat,
           const float* __restrict__ centers, const int* __restrict__ nbr,
           const float* __restrict__ w1, const float* __restrict__ b1,
           const float* __restrict__ g1, const float* __restrict__ be1,
           const float* __restrict__ w2, const float* __restrict__ b2,
           const float* __restrict__ g2, const float* __restrict__ be2,
           float* __restrict__ out) {
    __shared__ __align__(16) float s_h1[32][272];   // also hosts s_comb overlay
    __shared__ float s_wmax[4][128];
    __shared__ int s_nbr[32];
    __shared__ float s_ctr[3];

    float (*s_comb)[68] = (float(*)[68]) & s_h1[0][0];  // overlay, dead pre-LN

    int cid = blockIdx.x;
    int b = cid >> 11;
    int tid = threadIdx.x, w = tid >> 5, l = tid & 31;
    const int k0 = 8 * w;

    if (tid < 32) s_nbr[tid] = nbr[cid * KK + tid];
    if (tid < 3) s_ctr[tid] = centers[(size_t)cid * 3 + tid];
    __syncthreads();

    // gather comb = [features(64), rel(3)]
#pragma unroll
    for (int r = 0; r < 8; r++) {
        int k = k0 + r;
        int idx = s_nbr[k];
        const float2* frow = (const float2*)(feat + ((size_t)b * NN + idx) * CC);
        float2 v = frow[l];
        s_comb[k][2 * l] = v.x;
        s_comb[k][2 * l + 1] = v.y;
        if (l == 0) {
            const float* p = x + ((size_t)b * NN + idx) * 3;
            s_comb[k][64] = p[0] - s_ctr[0];
            s_comb[k][65] = p[1] - s_ctr[1];
            s_comb[k][66] = p[2] - s_ctr[2];
        }
    }
    __syncthreads();

    // ---- layer 1: lane cols 4l..4l+3, 128+4l..+3, 256+l (l<12); 8 rows/warp
    const int jA = 4 * l, jB = 128 + 4 * l, jC = 256 + l;
    const bool hasC = (l < 12);

    u64 accP[8][4];
    float acc9[8];
#pragma unroll
    for (int r = 0; r < 8; r++) {
        acc9[r] = 0.f;
#pragma unroll
        for (int q = 0; q < 4; q++) accP[r][q] = 0ull;
    }

    for (int i4 = 0; i4 < 16; i4++) {  // i = 0..63
        float4 cv4[8];
#pragma unroll
        for (int r = 0; r < 8; r++)
            cv4[r] = *(const float4*)&s_comb[k0 + r][i4 * 4];
#pragma unroll
        for (int ii = 0; ii < 4; ii++) {
            const float* wr = w1 + (i4 * 4 + ii) * HID;
            float4 wa = *(const float4*)(wr + jA);
            float4 wb = *(const float4*)(wr + jB);
            float wc = hasC ? wr[jC] : 0.f;
            u64 pw0 = pk2(wa.x, wa.y), pw1 = pk2(wa.z, wa.w);
            u64 pw2 = pk2(wb.x, wb.y), pw3 = pk2(wb.z, wb.w);
#pragma unroll
            for (int r = 0; r < 8; r++) {
                float c = (ii == 0) ? cv4[r].x
                        : (ii == 1) ? cv4[r].y
                        : (ii == 2) ? cv4[r].z : cv4[r].w;
                u64 cp = pk2(c, c);
                accP[r][0] = f2fma(cp, pw0, accP[r][0]);
                accP[r][1] = f2fma(cp, pw1, accP[r][1]);
                accP[r][2] = f2fma(cp, pw2, accP[r][2]);
                accP[r][3] = f2fma(cp, pw3, accP[r][3]);
                acc9[r] = __fmaf_rn(c, wc, acc9[r]);
            }
        }
    }
    for (int i = 64; i < CIN; i++) {  // tail
        const float* wr = w1 + i * HID;
        float4 wa = *(const float4*)(wr + jA);
        float4 wb = *(const float4*)(wr + jB);
        float wc = hasC ? wr[jC] : 0.f;
        u64 pw0 = pk2(wa.x, wa.y), pw1 = pk2(wa.z, wa.w);
        u64 pw2 = pk2(wb.x, wb.y), pw3 = pk2(wb.z, wb.w);
#pragma unroll
        for (int r = 0; r < 8; r++) {
            float c = s_comb[k0 + r][i];
            u64 cp = pk2(c, c);
            accP[r][0] = f2fma(cp, pw0, accP[r][0]);
            accP[r][1] = f2fma(cp, pw1, accP[r][1]);
            accP[r][2] = f2fma(cp, pw2, accP[r][2]);
            accP[r][3] = f2fma(cp, pw3, accP[r][3]);
            acc9[r] = __fmaf_rn(c, wc, acc9[r]);
        }
    }

    // all comb reads are done block-wide before s_h1 (overlay) is written
    __syncthreads();

    float acc[8][9];
#pragma unroll
    for (int r = 0; r < 8; r++) {
        upk2(accP[r][0], acc[r][0], acc[r][1]);
        upk2(accP[r][1], acc[r][2], acc[r][3]);
        upk2(accP[r][2], acc[r][4], acc[r][5]);
        upk2(accP[r][3], acc[r][6], acc[r][7]);
        acc[r][8] = acc9[r];
    }

    // bias + gelu
    {
        float4 bA = *(const float4*)(b1 + jA);
        float4 bB = *(const float4*)(b1 + jB);
        float bC = hasC ? b1[jC] : 0.f;
        float bias[9] = {bA.x, bA.y, bA.z, bA.w, bB.x, bB.y, bB.z, bB.w, bC};
#pragma unroll
        for (int r = 0; r < 8; r++)
#pragma unroll
            for (int c = 0; c < 9; c++)
                acc[r][c] = fast_gelu(acc[r][c] + bias[c]);
    }

    // LN over 268 (warp-wide)
    float sum[8], sq[8];
#pragma unroll
    for (int r = 0; r < 8; r++) {
        float s = 0.f, q = 0.f;
#pragma unroll
        for (int c = 0; c < 8; c++) {
            s += acc[r][c];
            q += acc[r][c] * acc[r][c];
        }
        if (hasC) {
            s += acc[r][8];
            q += acc[r][8] * acc[r][8];
        }
        sum[r] = s;
        sq[r] = q;
    }
#pragma unroll
    for (int o = 16; o; o >>= 1) {
#pragma unroll
        for (int r = 0; r < 8; r++) {
            sum[r] += __shfl_xor_sync(0xffffffffu, sum[r], o);
            sq[r] += __shfl_xor_sync(0xffffffffu, sq[r], o);
        }
    }
    {
        float4 gA = *(const float4*)(g1 + jA);
        float4 gB = *(const float4*)(g1 + jB);
        float gC = hasC ? g1[jC] : 0.f;
        float4 eA = *(const float4*)(be1 + jA);
        float4 eB = *(const float4*)(be1 + jB);
        float eC = hasC ? be1[jC] : 0.f;
        float gam[9] = {gA.x, gA.y, gA.z, gA.w, gB.x, gB.y, gB.z, gB.w, gC};
        float bet[9] = {eA.x, eA.y, eA.z, eA.w, eB.x, eB.y, eB.z, eB.w, eC};
#pragma unroll
        for (int r = 0; r < 8; r++) {
            float mu = sum[r] * (1.0f / 268.0f);
            float var = sq[r] * (1.0f / 268.0f) - mu * mu;
            float inv = rsqrtf(var + 1e-6f);
            int k = k0 + r;
            float o9[9];
#pragma unroll
            for (int c = 0; c < 9; c++)
                o9[c] = (acc[r][c] - mu) * inv * gam[c] + bet[c];
            *(float4*)&s_h1[k][jA] = make_float4(o9[0], o9[1], o9[2], o9[3]);
            *(float4*)&s_h1[k][jB] = make_float4(o9[4], o9[5], o9[6], o9[7]);
            if (hasC) s_h1[k][jC] = o9[8];
        }
    }
    __syncthreads();

    // ---- layer 2: 8 rows/warp, lane cols 4l..4l+3 (packed pairs)
    const int o0 = 4 * l;
    u64 a2p[8][2];
#pragma unroll
    for (int r = 0; r < 8; r++) { a2p[r][0] = 0ull; a2p[r][1] = 0ull; }

    for (int j4 = 0; j4 < HID / 4; j4++) {  // 67 chunks, exact
        float4 h4[8];
#pragma unroll
        for (int r = 0; r < 8; r++)
            h4[r] = *(const float4*)&s_h1[k0 + r][j4 * 4];
#pragma unroll
        for (int jj = 0; jj < 4; jj++) {
            int j = j4 * 4 + jj;
            float4 wv = *(const float4*)(w2 + j * OUTD + o0);
            u64 pw0 = pk2(wv.x, wv.y), pw1 = pk2(wv.z, wv.w);
#pragma unroll
            for (int r = 0; r < 8; r++) {
                float hv = (jj == 0) ? h4[r].x
                         : (jj == 1) ? h4[r].y
                         : (jj == 2) ? h4[r].z : h4[r].w;
                u64 hp = pk2(hv, hv);
                a2p[r][0] = f2fma(hp, pw0, a2p[r][0]);
                a2p[r][1] = f2fma(hp, pw1, a2p[r][1]);
            }
        }
    }

    float a2[8][4];
#pragma unroll
    for (int r = 0; r < 8; r++) {
        upk2(a2p[r][0], a2[r][0], a2[r][1]);
        upk2(a2p[r][1], a2[r][2], a2[r][3]);
    }
    {
        float4 bv = *(const float4*)(b2 + o0);
        float bias[4] = {bv.x, bv.y, bv.z, bv.w};
#pragma unroll
        for (int r = 0; r < 8; r++)
#pragma unroll
            for (int c = 0; c < 4; c++) a2[r][c] += bias[c];
    }
    // LN over 128 (warp-wide)
    float s2[8], q2[8];
#pragma unroll
    for (int r = 0; r < 8; r++) {
        float s = 0.f, q = 0.f;
#pragma unroll
        for (int c = 0; c < 4; c++) {
            s += a2[r][c];
            q += a2[r][c] * a2[r][c];
        }
        s2[r] = s;
        q2[r] = q;
    }
#pragma unroll
    for (int o = 16; o; o >>= 1) {
#pragma unroll
        for (int r = 0; r < 8; r++) {
            s2[r] += __shfl_xor_sync(0xffffffffu, s2[r], o);
            q2[r] += __shfl_xor_sync(0xffffffffu, q2[r], o);
        }
    }
    {
        float4 gv = *(const float4*)(g2 + o0);
        float4 ev = *(const float4*)(be2 + o0);
        float gam[4] = {gv.x, gv.y, gv.z, gv.w};
        float bet[4] = {ev.x, ev.y, ev.z, ev.w};
        float cmax[4];
#pragma unroll
        for (int c = 0; c < 4; c++) cmax[c] = -3.4e38f;
#pragma unroll
        for (int r = 0; r < 8; r++) {
            float mu = s2[r] * (1.0f / 128.0f);
            float var = q2[r] * (1.0f / 128.0f) - mu * mu;
            float inv = rsqrtf(var + 1e-6f);
#pragma unroll
            for (int c = 0; c < 4; c++) {
                float v = (a2[r][c] - mu) * inv * gam[c] + bet[c];
                cmax[c] = fmaxf(cmax[c], v);
            }
        }
#pragma unroll
        for (int c = 0; c < 4; c++) s_wmax[w][o0 + c] = cmax[c];
    }
    __syncthreads();
    if (tid < 128) {
        float m = s_wmax[0][tid];
#pragma unroll
        for (int ww = 1; ww < 4; ww++) m = fmaxf(m, s_wmax[ww][tid]);
        out[(size_t)cid * OUTD + tid] = m;
    }
}

// ---------------------------------------------------------------------------
extern "C" void kernel_launch(void* const* d_in, const int* in_sizes, int n_in,
                              void* d_out, int out_size) {
    const float* x = (const float*)d_in[0];
    const float* feat = (const float*)d_in[1];
    const int* first_idx = (const int*)d_in[2];
    const float* w1 = (const float*)d_in[3];
    const float* b1 = (const float*)d_in[4];
    const float* g1 = (const float*)d_in[5];
    const float* be1 = (const float*)d_in[6];
    const float* w2 = (const float*)d_in[7];
    const float* b2 = (const float*)d_in[8];
    const float* g2 = (const float*)d_in[9];
    const float* be2 = (const float*)d_in[10];

    float* centers = (float*)d_out;                    // [B, M, 3]
    float* out = (float*)d_out + (size_t)BB * MM * 3;  // [B, M, 128]

    int* nbr;
    cudaGetSymbolAddress((void**)&nbr, g_nbr);

    const int fps_smem = 3 * NN * (int)sizeof(float);  // 96KB coords mirror
    cudaFuncSetAttribute(fps_kernel, cudaFuncAttributeMaxDynamicSharedMemorySize,
                         fps_smem);

    fps_kernel<<<BB, 1024, fps_smem>>>(x, first_idx, centers);
    bq_kernel<<<BB * MM / 4, 128>>>(x, centers, nbr);
    mlp_kernel<<<BB * MM, 128>>>(x, feat, centers, nbr, w1, b1, g1, be1, w2, b2,
                                 g2, be2, out);
}